// round 2
// baseline (speedup 1.0000x reference)
#include <cuda_runtime.h>

// ---------------- problem constants (fixed by the dataset) ----------------
#define Bn     16
#define SEQn   256
#define DIMn   1024
#define HEADSn 16
#define DHEADn 64
#define INNERn 1024
#define Mmem   8
#define TXTn   77
#define KVn    (Mmem*SEQn + TXTn)   // 2125
#define MSn    (Mmem*SEQn)          // 2048
#define SCALEf 0.125f               // 64^-0.5

#define ROWS_X   (Bn*SEQn)          // 4096
#define ROWS_C   (Bn*KVn)           // 34000
#define BHn      (Bn*HEADSn)        // 256

// ---------------- scratch (device globals: no allocation allowed) ---------
__device__ float g_Q[ROWS_X * INNERn];              // 16.8 MB
__device__ float g_K[ROWS_C * INNERn];              // 139 MB
__device__ float g_V[ROWS_C * INNERn];              // 139 MB
__device__ float g_S[(long long)BHn * SEQn * KVn];  // 557 MB
__device__ float g_O[ROWS_X * INNERn];              // 16.8 MB

// ---------------- generic tiled fp32 GEMM ---------------------------------
// C[m,n] = alpha * sum_k A[m,k] * (TB ? B[n,k] : B[k,n])  (+ bias[n])
// Batched via blockIdx.z: z -> (zb = z/H, zh = z%H), pointer offsets
// A += zb*sAb + zh*sAh, etc.  Fully bounds-guarded in M, N, K.
template<int BM, int BN, int BK, int TM, int TN, bool TB, bool BIAS>
__global__ __launch_bounds__((BM/TM)*(BN/TN))
void gemm_k(const float* __restrict__ Aall, const float* __restrict__ Ball,
            float* __restrict__ Call, const float* __restrict__ bias,
            float alpha, int M, int N, int K,
            int lda, int ldb, int ldc, int H,
            long long sAb, long long sAh,
            long long sBb, long long sBh,
            long long sCb, long long sCh)
{
    constexpr int NTHR = (BM/TM)*(BN/TN);
    __shared__ float As[BK][BM];
    __shared__ float Bs[BK][BN];

    const int z  = blockIdx.z;
    const int zb = z / H, zh = z - zb * H;
    const float* A = Aall + zb*sAb + zh*sAh;
    const float* Bp = Ball + zb*sBb + zh*sBh;
    float*       C  = Call + zb*sCb + zh*sCh;

    const int m0 = blockIdx.y * BM;
    const int n0 = blockIdx.x * BN;
    const int tid  = threadIdx.x;
    const int tcol = tid % (BN/TN);
    const int trow = tid / (BN/TN);

    float acc[TM][TN];
#pragma unroll
    for (int i = 0; i < TM; i++)
#pragma unroll
        for (int j = 0; j < TN; j++) acc[i][j] = 0.f;

    for (int k0 = 0; k0 < K; k0 += BK) {
        // --- load A tile (BM x BK), transposed into smem ---
#pragma unroll
        for (int e = tid; e < BM*BK; e += NTHR) {
            int r = e / BK, c = e % BK;
            int gm = m0 + r, gk = k0 + c;
            As[c][r] = (gm < M && gk < K) ? A[(long long)gm*lda + gk] : 0.f;
        }
        // --- load B tile ---
        if (!TB) {
#pragma unroll
            for (int e = tid; e < BK*BN; e += NTHR) {
                int r = e / BN, c = e % BN;
                int gk = k0 + r, gn = n0 + c;
                Bs[r][c] = (gk < K && gn < N) ? Bp[(long long)gk*ldb + gn] : 0.f;
            }
        } else {
#pragma unroll
            for (int e = tid; e < BN*BK; e += NTHR) {
                int r = e / BK, c = e % BK;   // r: n index, c: k index
                int gn = n0 + r, gk = k0 + c;
                Bs[c][r] = (gn < N && gk < K) ? Bp[(long long)gn*ldb + gk] : 0.f;
            }
        }
        __syncthreads();

#pragma unroll
        for (int kk = 0; kk < BK; kk++) {
            float a[TM], b[TN];
#pragma unroll
            for (int i = 0; i < TM; i++) a[i] = As[kk][trow*TM + i];
#pragma unroll
            for (int j = 0; j < TN; j++) b[j] = Bs[kk][tcol*TN + j];
#pragma unroll
            for (int i = 0; i < TM; i++)
#pragma unroll
                for (int j = 0; j < TN; j++)
                    acc[i][j] = fmaf(a[i], b[j], acc[i][j]);
        }
        __syncthreads();
    }

#pragma unroll
    for (int i = 0; i < TM; i++) {
        int gm = m0 + trow*TM + i;
        if (gm >= M) continue;
#pragma unroll
        for (int j = 0; j < TN; j++) {
            int gn = n0 + tcol*TN + j;
            if (gn >= N) continue;
            float v = alpha * acc[i][j];
            if (BIAS) v += bias[gn];
            C[(long long)gm*ldc + gn] = v;
        }
    }
}

// ---------------- rotary on Q ---------------------------------------------
// Q layout: [(b*SEQ+s), h*64+d]. src freqs: freqs[rs*16 + s/16][cs*16 + s%16][d]
__global__ void rotary_q_kernel(float* __restrict__ Q, const float* __restrict__ freqs,
                                const int* __restrict__ cur)
{
    const int row = blockIdx.x;          // b*SEQ + s
    const int s   = row % SEQn;
    const int p   = threadIdx.x;         // 0..511 pair index
    const int col0 = 2*p;
    const int d0   = col0 & 63;

    const int cp = cur[0];
    const int inner = cp % 16;
    const int rs = inner % 4, cs = inner / 4;
    const int fr = rs*16 + (s >> 4), fc = cs*16 + (s & 15);
    const float* f = freqs + ((fr<<6) + fc) * 64;
    const float f0 = f[d0], f1 = f[d0+1];

    float* q = Q + (long long)row*INNERn + col0;
    const float t0 = q[0], t1 = q[1];
    q[0] = t0*cosf(f0) - t1*sinf(f0);
    q[1] = t1*cosf(f1) + t0*sinf(f1);
}

// ---------------- bias + rotary on memory K rows ---------------------------
__global__ void biasrot_k_kernel(float* __restrict__ K, const float* __restrict__ freqs,
                                 const float* __restrict__ rel_table,
                                 const int* __restrict__ memidx,
                                 const int* __restrict__ cur)
{
    const int gid = blockIdx.x;          // b*MS + j
    const int b = gid / MSn;
    const int j = gid - b*MSn;
    const int m = j >> 8;                // j / 256
    const int jj = j & 255;

    const int p = threadIdx.x;
    const int col0 = 2*p;
    const int h  = col0 >> 6;
    const int d0 = col0 & 63;

    const int cp = cur[0];
    const int ci = cp % 16;
    const int rs = ci % 4, cs = ci / 4, ts = cp / 16;
    const int mi = memidx[m];
    const int mn = mi % 16;
    const int rt = mn % 4, ct = mn / 4, tt = mi / 16;
    const int rel = (rt - rs + 4)*9 + (ct - cs + 4) + (tt - ts + 4)*81;
    const float bias = rel_table[rel*HEADSn + h];

    const int fr = rt*16 + (jj >> 4), fc = ct*16 + (jj & 15);
    const float* f = freqs + ((fr<<6) + fc) * 64;
    const float f0 = f[d0], f1 = f[d0+1];

    float* kp = K + ((long long)b*KVn + j)*INNERn + col0;
    const float t0 = kp[0] + bias, t1 = kp[1] + bias;
    kp[0] = t0*cosf(f0) - t1*sinf(f0);
    kp[1] = t1*cosf(f1) + t0*sinf(f1);
}

// ---------------- row softmax over KV --------------------------------------
__global__ void softmax_kernel(float* __restrict__ S, int ncols)
{
    const long long row = blockIdx.x;
    float* p = S + row * ncols;
    const int tid = threadIdx.x;
    __shared__ float red[256];

    float m = -1e30f;
    for (int j = tid; j < ncols; j += 256) m = fmaxf(m, p[j]);
    red[tid] = m; __syncthreads();
    for (int s = 128; s > 0; s >>= 1) {
        if (tid < s) red[tid] = fmaxf(red[tid], red[tid + s]);
        __syncthreads();
    }
    m = red[0];
    __syncthreads();

    float sum = 0.f;
    for (int j = tid; j < ncols; j += 256) {
        float e = __expf(p[j] - m);
        p[j] = e;
        sum += e;
    }
    red[tid] = sum; __syncthreads();
    for (int s = 128; s > 0; s >>= 1) {
        if (tid < s) red[tid] += red[tid + s];
        __syncthreads();
    }
    const float inv = 1.f / red[0];
    for (int j = tid; j < ncols; j += 256) p[j] *= inv;
}

// ---------------- host launch ----------------------------------------------
extern "C" void kernel_launch(void* const* d_in, const int* in_sizes, int n_in,
                              void* d_out, int out_size)
{
    const float* x     = (const float*)d_in[0];
    const float* cond  = (const float*)d_in[1];
    const float* freqs = (const float*)d_in[2];
    const float* Wq    = (const float*)d_in[3];
    const float* Wk    = (const float*)d_in[4];
    const float* Wv    = (const float*)d_in[5];
    const float* rel   = (const float*)d_in[6];
    const float* Wo    = (const float*)d_in[7];
    const float* bo    = (const float*)d_in[8];
    const int*   memi  = (const int*)d_in[9];
    const int*   cur   = (const int*)d_in[10];
    float* out = (float*)d_out;

    float *Qb, *Kb, *Vb, *Sb, *Ob;
    cudaGetSymbolAddress((void**)&Qb, g_Q);
    cudaGetSymbolAddress((void**)&Kb, g_K);
    cudaGetSymbolAddress((void**)&Vb, g_V);
    cudaGetSymbolAddress((void**)&Sb, g_S);
    cudaGetSymbolAddress((void**)&Ob, g_O);

    const dim3 blk(256);

    // 1) Q = x @ Wq            (4096 x 1024 x 1024)
    gemm_k<128,128,8,8,8,false,false><<<dim3(8,32,1), blk>>>(
        x, Wq, Qb, nullptr, 1.f,
        ROWS_X, INNERn, DIMn, DIMn, INNERn, INNERn,
        1, 0,0, 0,0, 0,0);

    // 2) K = cond @ Wk         (34000 x 1024 x 1024)
    gemm_k<128,128,8,8,8,false,false><<<dim3(8,266,1), blk>>>(
        cond, Wk, Kb, nullptr, 1.f,
        ROWS_C, INNERn, DIMn, DIMn, INNERn, INNERn,
        1, 0,0, 0,0, 0,0);

    // 3) V = cond @ Wv
    gemm_k<128,128,8,8,8,false,false><<<dim3(8,266,1), blk>>>(
        cond, Wv, Vb, nullptr, 1.f,
        ROWS_C, INNERn, DIMn, DIMn, INNERn, INNERn,
        1, 0,0, 0,0, 0,0);

    // 4) rotary(Q)
    rotary_q_kernel<<<ROWS_X, 512>>>(Qb, freqs, cur);

    // 5) bias + rotary on memory K rows
    biasrot_k_kernel<<<Bn*MSn, 512>>>(Kb, freqs, rel, memi, cur);

    // 6) S = scale * Q @ K^T, batched over (b,h)   (256 x 2125 x 64 per z)
    gemm_k<128,128,8,8,8,true,false><<<dim3(17,2,BHn), blk>>>(
        Qb, Kb, Sb, nullptr, SCALEf,
        SEQn, KVn, DHEADn, INNERn, INNERn, KVn,
        HEADSn,
        (long long)SEQn*INNERn, (long long)DHEADn,          // A: Q
        (long long)KVn*INNERn,  (long long)DHEADn,          // B: K
        (long long)HEADSn*SEQn*KVn, (long long)SEQn*KVn);   // C: S

    // 7) softmax rows
    softmax_kernel<<<BHn*SEQn, 256>>>(Sb, KVn);

    // 8) O = P @ V, batched     (256 x 64 x 2125 per z)
    gemm_k<128,64,8,8,4,false,false><<<dim3(1,2,BHn), blk>>>(
        Sb, Vb, Ob, nullptr, 1.f,
        SEQn, DHEADn, KVn, KVn, INNERn, INNERn,
        HEADSn,
        (long long)HEADSn*SEQn*KVn, (long long)SEQn*KVn,    // A: S
        (long long)KVn*INNERn, (long long)DHEADn,           // B: V
        (long long)SEQn*INNERn, (long long)DHEADn);         // C: O

    // 9) out = O @ Wo + bo
    gemm_k<128,128,8,8,8,false,true><<<dim3(8,32,1), blk>>>(
        Ob, Wo, out, bo, 1.f,
        ROWS_X, DIMn, INNERn, INNERn, DIMn, DIMn,
        1, 0,0, 0,0, 0,0);
}

// round 4
// speedup vs baseline: 1.9879x; 1.9879x over previous
#include <cuda_runtime.h>
#include <cstdint>
#include <cstddef>

// ---------------- problem constants (fixed by the dataset) ----------------
#define Bn     16
#define SEQn   256
#define DIMn   1024
#define HEADSn 16
#define DHEADn 64
#define INNERn 1024
#define Mmem   8
#define TXTn   77
#define KVn    (Mmem*SEQn + TXTn)   // 2125
#define MSn    (Mmem*SEQn)          // 2048
#define SCALEf 0.125f               // 64^-0.5

#define ROWS_X   (Bn*SEQn)          // 4096
#define ROWS_C   (Bn*KVn)           // 34000
#define BHn      (Bn*HEADSn)        // 256

// ---------------- scratch (device globals: no allocation allowed) ---------
__device__ float g_Q[ROWS_X * INNERn];              // 16.8 MB
__device__ float g_K[ROWS_C * INNERn];              // 139 MB
__device__ float g_V[ROWS_C * INNERn];              // 139 MB
__device__ float g_S[(long long)BHn * SEQn * KVn];  // 557 MB
__device__ float g_O[ROWS_X * INNERn];              // 16.8 MB
__device__ float g_Wt[4 * DIMn * INNERn];           // transposed+rounded weights
__device__ float g_Xr[ROWS_X * DIMn];               // rounded x
__device__ float g_Cr[ROWS_C * DIMn];               // rounded cond

// ---------------- helpers --------------------------------------------------
__device__ __forceinline__ uint32_t smem_u32(const void* p) {
    uint32_t a;
    asm("{ .reg .u64 t; cvta.to.shared.u64 t, %1; cvt.u32.u64 %0, t; }" : "=r"(a) : "l"(p));
    return a;
}
__device__ __forceinline__ float rna_tf32(float x) {
    float y;
    asm("cvt.rna.tf32.f32 %0, %1;" : "=f"(y) : "f"(x));
    return y;
}

// =================== tf32 mma.sync GEMM ====================================
// C[M,1024] = A[M,1024] @ Bt[n][k]^T   (Bt K-major, N = K = 1024 fixed)
// Inputs MUST already be tf32-rounded (rna).  Tile 128x128x16, 256 threads,
// 8 warps in 2(m) x 4(n), warp tile 64x32, mma m16n8k8, cp.async double-buffer.
#define SA_STR 20   // smem row stride in floats (bank-conflict-free fragments)

template<bool BIAS>
__global__ __launch_bounds__(256)
void gemm_mma(const float* __restrict__ A, const float* __restrict__ Bt,
              float* __restrict__ C, const float* __restrict__ bias, int M)
{
    __shared__ float As[2][128 * SA_STR];
    __shared__ float Bs[2][128 * SA_STR];

    const int tid  = threadIdx.x;
    const int wid  = tid >> 5, lane = tid & 31;
    const int g    = lane >> 2, tg = lane & 3;
    const int wm   = (wid >> 2) * 64;   // warp m offset (0 or 64)
    const int wn   = (wid & 3) * 32;    // warp n offset
    const int m0   = blockIdx.y * 128, n0 = blockIdx.x * 128;

    float d[4][4][4];
#pragma unroll
    for (int i = 0; i < 4; i++)
#pragma unroll
        for (int j = 0; j < 4; j++)
#pragma unroll
            for (int q = 0; q < 4; q++) d[i][j][q] = 0.f;

    auto issue = [&](int buf, int kt) {
        const int k0 = kt * 16;
#pragma unroll
        for (int e = 0; e < 2; e++) {
            int idx = tid + e * 256;        // 0..511
            int row = idx >> 2, c4 = idx & 3;
            // A (guard M)
            int ga = m0 + row;
            int pa = (ga < M) ? 16 : 0;
            if (ga >= M) ga = M - 1;
            uint32_t da = smem_u32(&As[buf][row * SA_STR + c4 * 4]);
            const float* sa = A + (size_t)ga * 1024u + k0 + c4 * 4;
            asm volatile("cp.async.cg.shared.global [%0], [%1], 16, %2;"
                         :: "r"(da), "l"(sa), "r"(pa));
            // B (always in bounds)
            uint32_t db = smem_u32(&Bs[buf][row * SA_STR + c4 * 4]);
            const float* sb = Bt + (size_t)(n0 + row) * 1024u + k0 + c4 * 4;
            asm volatile("cp.async.cg.shared.global [%0], [%1], 16;"
                         :: "r"(db), "l"(sb));
        }
        asm volatile("cp.async.commit_group;" ::: "memory");
    };

    issue(0, 0);
    issue(1, 1);

    for (int kt = 0; kt < 64; kt++) {
        const int buf = kt & 1;
        if (kt < 63) asm volatile("cp.async.wait_group 1;" ::: "memory");
        else         asm volatile("cp.async.wait_group 0;" ::: "memory");
        __syncthreads();

#pragma unroll
        for (int ks = 0; ks < 2; ks++) {
            uint32_t af[4][4], bf[4][2];
#pragma unroll
            for (int i = 0; i < 4; i++) {
                const float* base = &As[buf][(wm + i * 16) * SA_STR + ks * 8];
                af[i][0] = __float_as_uint(base[(g)     * SA_STR + tg]);
                af[i][1] = __float_as_uint(base[(g + 8) * SA_STR + tg]);
                af[i][2] = __float_as_uint(base[(g)     * SA_STR + tg + 4]);
                af[i][3] = __float_as_uint(base[(g + 8) * SA_STR + tg + 4]);
            }
#pragma unroll
            for (int j = 0; j < 4; j++) {
                const float* base = &Bs[buf][(wn + j * 8 + g) * SA_STR + ks * 8];
                bf[j][0] = __float_as_uint(base[tg]);
                bf[j][1] = __float_as_uint(base[tg + 4]);
            }
#pragma unroll
            for (int i = 0; i < 4; i++)
#pragma unroll
                for (int j = 0; j < 4; j++)
                    asm volatile(
                        "mma.sync.aligned.m16n8k8.row.col.f32.tf32.tf32.f32 "
                        "{%0,%1,%2,%3},{%4,%5,%6,%7},{%8,%9},{%0,%1,%2,%3};"
                        : "+f"(d[i][j][0]), "+f"(d[i][j][1]),
                          "+f"(d[i][j][2]), "+f"(d[i][j][3])
                        : "r"(af[i][0]), "r"(af[i][1]), "r"(af[i][2]), "r"(af[i][3]),
                          "r"(bf[j][0]), "r"(bf[j][1]));
        }
        __syncthreads();
        if (kt + 2 < 64) issue(buf, kt + 2);
    }

    // epilogue
#pragma unroll
    for (int i = 0; i < 4; i++) {
        const int r0 = m0 + wm + i * 16 + g;
#pragma unroll
        for (int j = 0; j < 4; j++) {
            const int c = n0 + wn + j * 8 + tg * 2;
            float2 v0 = make_float2(d[i][j][0], d[i][j][1]);
            float2 v1 = make_float2(d[i][j][2], d[i][j][3]);
            if (BIAS) {
                const float b0 = bias[c], b1 = bias[c + 1];
                v0.x += b0; v0.y += b1; v1.x += b0; v1.y += b1;
            }
            if (r0 < M)     *(float2*)&C[(size_t)r0 * 1024u + c] = v0;
            if (r0 + 8 < M) *(float2*)&C[(size_t)(r0 + 8) * 1024u + c] = v1;
        }
    }
}

// ---------------- weight transpose + tf32 round: Wt[n][k] = rna(W[k][n]) ---
__global__ void transpose_1024(const float* __restrict__ W, float* __restrict__ Wt)
{
    __shared__ float t[32][33];
    const int bx = blockIdx.x * 32, by = blockIdx.y * 32;
    const int tx = threadIdx.x, ty = threadIdx.y;
#pragma unroll
    for (int i = 0; i < 4; i++)
        t[ty + i * 8][tx] = W[(size_t)(by + ty + i * 8) * 1024 + bx + tx];
    __syncthreads();
#pragma unroll
    for (int i = 0; i < 4; i++)
        Wt[(size_t)(bx + ty + i * 8) * 1024 + by + tx] = rna_tf32(t[tx][ty + i * 8]);
}

// ---------------- tf32 rounding copy ---------------------------------------
__global__ void round_copy(const float4* __restrict__ in, float4* __restrict__ out, int n4)
{
    int i = blockIdx.x * blockDim.x + threadIdx.x;
    if (i < n4) {
        float4 v = in[i];
        v.x = rna_tf32(v.x); v.y = rna_tf32(v.y);
        v.z = rna_tf32(v.z); v.w = rna_tf32(v.w);
        out[i] = v;
    }
}

// ---------------- generic tiled fp32 GEMM (S and PV) -----------------------
template<int BM, int BN, int BK, int TM, int TN, bool TB, bool RND>
__global__ __launch_bounds__((BM/TM)*(BN/TN))
void gemm_k(const float* __restrict__ Aall, const float* __restrict__ Ball,
            float* __restrict__ Call,
            float alpha, int M, int N, int K,
            int lda, int ldb, int ldc, int H,
            long long sAb, long long sAh,
            long long sBb, long long sBh,
            long long sCb, long long sCh)
{
    constexpr int NTHR = (BM/TM)*(BN/TN);
    __shared__ float As[BK][BM];
    __shared__ float Bs[BK][BN];

    const int z  = blockIdx.z;
    const int zb = z / H, zh = z - zb * H;
    const float* A  = Aall + zb*sAb + zh*sAh;
    const float* Bp = Ball + zb*sBb + zh*sBh;
    float*       C  = Call + zb*sCb + zh*sCh;

    const int m0 = blockIdx.y * BM;
    const int n0 = blockIdx.x * BN;
    const int tid  = threadIdx.x;
    const int tcol = tid % (BN/TN);
    const int trow = tid / (BN/TN);

    float acc[TM][TN];
#pragma unroll
    for (int i = 0; i < TM; i++)
#pragma unroll
        for (int j = 0; j < TN; j++) acc[i][j] = 0.f;

    for (int k0 = 0; k0 < K; k0 += BK) {
#pragma unroll
        for (int e = tid; e < BM*BK; e += NTHR) {
            int r = e / BK, c = e % BK;
            int gm = m0 + r, gk = k0 + c;
            As[c][r] = (gm < M && gk < K) ? A[(long long)gm*lda + gk] : 0.f;
        }
        if (!TB) {
#pragma unroll
            for (int e = tid; e < BK*BN; e += NTHR) {
                int r = e / BN, c = e % BN;
                int gk = k0 + r, gn = n0 + c;
                Bs[r][c] = (gk < K && gn < N) ? Bp[(long long)gk*ldb + gn] : 0.f;
            }
        } else {
#pragma unroll
            for (int e = tid; e < BN*BK; e += NTHR) {
                int r = e / BK, c = e % BK;
                int gn = n0 + r, gk = k0 + c;
                Bs[c][r] = (gn < N && gk < K) ? Bp[(long long)gn*ldb + gk] : 0.f;
            }
        }
        __syncthreads();

#pragma unroll
        for (int kk = 0; kk < BK; kk++) {
            float a[TM], b[TN];
#pragma unroll
            for (int i = 0; i < TM; i++) a[i] = As[kk][trow*TM + i];
#pragma unroll
            for (int j = 0; j < TN; j++) b[j] = Bs[kk][tcol*TN + j];
#pragma unroll
            for (int i = 0; i < TM; i++)
#pragma unroll
                for (int j = 0; j < TN; j++)
                    acc[i][j] = fmaf(a[i], b[j], acc[i][j]);
        }
        __syncthreads();
    }

#pragma unroll
    for (int i = 0; i < TM; i++) {
        int gm = m0 + trow*TM + i;
        if (gm >= M) continue;
#pragma unroll
        for (int j = 0; j < TN; j++) {
            int gn = n0 + tcol*TN + j;
            if (gn >= N) continue;
            float v = alpha * acc[i][j];
            if (RND) v = rna_tf32(v);
            C[(long long)gm*ldc + gn] = v;
        }
    }
}

// ---------------- rotary on Q ---------------------------------------------
__global__ void rotary_q_kernel(float* __restrict__ Q, const float* __restrict__ freqs,
                                const int* __restrict__ cur)
{
    const int row = blockIdx.x;          // b*SEQ + s
    const int s   = row % SEQn;
    const int p   = threadIdx.x;
    const int col0 = 2*p;
    const int d0   = col0 & 63;

    const int cp = cur[0];
    const int inner = cp % 16;
    const int rs = inner % 4, cs = inner / 4;
    const int fr = rs*16 + (s >> 4), fc = cs*16 + (s & 15);
    const float* f = freqs + ((fr<<6) + fc) * 64;
    const float f0 = f[d0], f1 = f[d0+1];

    float* q = Q + (long long)row*INNERn + col0;
    const float t0 = q[0], t1 = q[1];
    q[0] = t0*cosf(f0) - t1*sinf(f0);
    q[1] = t1*cosf(f1) + t0*sinf(f1);
}

// ---------------- bias + rotary on memory K rows ---------------------------
__global__ void biasrot_k_kernel(float* __restrict__ K, const float* __restrict__ freqs,
                                 const float* __restrict__ rel_table,
                                 const int* __restrict__ memidx,
                                 const int* __restrict__ cur)
{
    const int gid = blockIdx.x;          // b*MS + j
    const int b = gid / MSn;
    const int j = gid - b*MSn;
    const int m = j >> 8;
    const int jj = j & 255;

    const int p = threadIdx.x;
    const int col0 = 2*p;
    const int h  = col0 >> 6;
    const int d0 = col0 & 63;

    const int cp = cur[0];
    const int ci = cp % 16;
    const int rs = ci % 4, cs = ci / 4, ts = cp / 16;
    const int mi = memidx[m];
    const int mn = mi % 16;
    const int rt = mn % 4, ct = mn / 4, tt = mi / 16;
    const int rel = (rt - rs + 4)*9 + (ct - cs + 4) + (tt - ts + 4)*81;
    const float bias = rel_table[rel*HEADSn + h];

    const int fr = rt*16 + (jj >> 4), fc = ct*16 + (jj & 15);
    const float* f = freqs + ((fr<<6) + fc) * 64;
    const float f0 = f[d0], f1 = f[d0+1];

    float* kp = K + ((long long)b*KVn + j)*INNERn + col0;
    const float t0 = kp[0] + bias, t1 = kp[1] + bias;
    kp[0] = t0*cosf(f0) - t1*sinf(f0);
    kp[1] = t1*cosf(f1) + t0*sinf(f1);
}

// ---------------- row softmax over KV --------------------------------------
__global__ void softmax_kernel(float* __restrict__ S, int ncols)
{
    const long long row = blockIdx.x;
    float* p = S + row * ncols;
    const int tid = threadIdx.x;
    __shared__ float red[256];

    float m = -1e30f;
    for (int j = tid; j < ncols; j += 256) m = fmaxf(m, p[j]);
    red[tid] = m; __syncthreads();
    for (int s = 128; s > 0; s >>= 1) {
        if (tid < s) red[tid] = fmaxf(red[tid], red[tid + s]);
        __syncthreads();
    }
    m = red[0];
    __syncthreads();

    float sum = 0.f;
    for (int j = tid; j < ncols; j += 256) {
        float e = __expf(p[j] - m);
        p[j] = e;
        sum += e;
    }
    red[tid] = sum; __syncthreads();
    for (int s = 128; s > 0; s >>= 1) {
        if (tid < s) red[tid] += red[tid + s];
        __syncthreads();
    }
    const float inv = 1.f / red[0];
    for (int j = tid; j < ncols; j += 256) p[j] *= inv;
}

// ---------------- host launch ----------------------------------------------
extern "C" void kernel_launch(void* const* d_in, const int* in_sizes, int n_in,
                              void* d_out, int out_size)
{
    const float* x     = (const float*)d_in[0];
    const float* cond  = (const float*)d_in[1];
    const float* freqs = (const float*)d_in[2];
    const float* Wq    = (const float*)d_in[3];
    const float* Wk    = (const float*)d_in[4];
    const float* Wv    = (const float*)d_in[5];
    const float* rel   = (const float*)d_in[6];
    const float* Wo    = (const float*)d_in[7];
    const float* bo    = (const float*)d_in[8];
    const int*   memi  = (const int*)d_in[9];
    const int*   cur   = (const int*)d_in[10];
    float* out = (float*)d_out;

    float *Qb, *Kb, *Vb, *Sb, *Ob, *Wt, *Xr, *Cr;
    cudaGetSymbolAddress((void**)&Qb, g_Q);
    cudaGetSymbolAddress((void**)&Kb, g_K);
    cudaGetSymbolAddress((void**)&Vb, g_V);
    cudaGetSymbolAddress((void**)&Sb, g_S);
    cudaGetSymbolAddress((void**)&Ob, g_O);
    cudaGetSymbolAddress((void**)&Wt, g_Wt);
    cudaGetSymbolAddress((void**)&Xr, g_Xr);
    cudaGetSymbolAddress((void**)&Cr, g_Cr);

    float* Wtq = Wt + 0LL * DIMn * INNERn;
    float* Wtk = Wt + 1LL * DIMn * INNERn;
    float* Wtv = Wt + 2LL * DIMn * INNERn;
    float* Wto = Wt + 3LL * DIMn * INNERn;

    // 0) tf32-round activations; transpose+round weights to K-major [N][K]
    round_copy<<<(ROWS_X*DIMn/4 + 255)/256, 256>>>((const float4*)x,    (float4*)Xr, ROWS_X*DIMn/4);
    round_copy<<<(ROWS_C*DIMn/4 + 255)/256, 256>>>((const float4*)cond, (float4*)Cr, ROWS_C*DIMn/4);
    transpose_1024<<<dim3(32,32), dim3(32,8)>>>(Wq, Wtq);
    transpose_1024<<<dim3(32,32), dim3(32,8)>>>(Wk, Wtk);
    transpose_1024<<<dim3(32,32), dim3(32,8)>>>(Wv, Wtv);
    transpose_1024<<<dim3(32,32), dim3(32,8)>>>(Wo, Wto);

    // 1-3) projections on tf32 tensor cores
    gemm_mma<false><<<dim3(8, 32),  256>>>(Xr, Wtq, Qb, nullptr, ROWS_X);
    gemm_mma<false><<<dim3(8, 266), 256>>>(Cr, Wtk, Kb, nullptr, ROWS_C);
    gemm_mma<false><<<dim3(8, 266), 256>>>(Cr, Wtv, Vb, nullptr, ROWS_C);

    // 4) rotary(Q)
    rotary_q_kernel<<<ROWS_X, 512>>>(Qb, freqs, cur);

    // 5) bias + rotary on memory K rows
    biasrot_k_kernel<<<Bn*MSn, 512>>>(Kb, freqs, rel, memi, cur);

    // 6) S = scale * Q @ K^T, batched over (b,h)  (fp32)
    gemm_k<128,128,8,8,8,true,false><<<dim3(17,2,BHn), dim3(256)>>>(
        Qb, Kb, Sb, SCALEf,
        SEQn, KVn, DHEADn, INNERn, INNERn, KVn,
        HEADSn,
        (long long)SEQn*INNERn, (long long)DHEADn,
        (long long)KVn*INNERn,  (long long)DHEADn,
        (long long)HEADSn*SEQn*KVn, (long long)SEQn*KVn);

    // 7) softmax rows
    softmax_kernel<<<BHn*SEQn, 256>>>(Sb, KVn);

    // 8) O = P @ V, batched (fp32), epilogue rounds O to tf32 for out-proj
    gemm_k<128,64,8,8,4,false,true><<<dim3(1,2,BHn), dim3(256)>>>(
        Sb, Vb, Ob, 1.f,
        SEQn, DHEADn, KVn, KVn, INNERn, INNERn,
        HEADSn,
        (long long)HEADSn*SEQn*KVn, (long long)SEQn*KVn,
        (long long)KVn*INNERn, (long long)DHEADn,
        (long long)SEQn*INNERn, (long long)DHEADn);

    // 9) out = O @ Wo + bo  (tf32 tensor cores, bias epilogue)
    gemm_mma<true><<<dim3(8, 32), 256>>>(Ob, Wto, out, bo, ROWS_X);
}

// round 6
// speedup vs baseline: 3.2011x; 1.6103x over previous
#include <cuda_runtime.h>
#include <cstdint>
#include <cstddef>

// ---------------- problem constants (fixed by the dataset) ----------------
#define Bn     16
#define SEQn   256
#define DIMn   1024
#define HEADSn 16
#define DHEADn 64
#define INNERn 1024
#define Mmem   8
#define TXTn   77
#define KVn    (Mmem*SEQn + TXTn)   // 2125
#define MSn    (Mmem*SEQn)          // 2048
#define SCALEf 0.125f               // 64^-0.5

#define ROWS_X   (Bn*SEQn)          // 4096
#define ROWS_C   (Bn*KVn)           // 34000
#define BHn      (Bn*HEADSn)        // 256

// ---------------- scratch (device globals: no allocation allowed) ---------
__device__ float g_Q[ROWS_X * INNERn];
__device__ float g_K[ROWS_C * INNERn];
__device__ float g_V[ROWS_C * INNERn];
__device__ float g_O[ROWS_X * INNERn];
__device__ float g_Wt[4 * DIMn * INNERn];
__device__ float g_Xr[ROWS_X * DIMn];
__device__ float g_Cr[ROWS_C * DIMn];

// ---------------- helpers --------------------------------------------------
__device__ __forceinline__ uint32_t smem_u32(const void* p) {
    uint32_t a;
    asm("{ .reg .u64 t; cvta.to.shared.u64 t, %1; cvt.u32.u64 %0, t; }" : "=r"(a) : "l"(p));
    return a;
}
__device__ __forceinline__ float rna_tf32(float x) {
    float y;
    asm("cvt.rna.tf32.f32 %0, %1;" : "=f"(y) : "f"(x));
    return y;
}
#define MMA_TF32(d0,d1,d2,d3,a0,a1,a2,a3,b0,b1)                               \
    asm volatile(                                                             \
        "mma.sync.aligned.m16n8k8.row.col.f32.tf32.tf32.f32 "                 \
        "{%0,%1,%2,%3},{%4,%5,%6,%7},{%8,%9},{%0,%1,%2,%3};"                  \
        : "+f"(d0), "+f"(d1), "+f"(d2), "+f"(d3)                              \
        : "r"(a0), "r"(a1), "r"(a2), "r"(a3), "r"(b0), "r"(b1))

// =================== tf32 mma.sync GEMM (projections) ======================
// C[M,1024] = A[M,1024] @ Bt[n][k]^T   (Bt K-major, N = K = 1024 fixed)
// Tile 128x128x16, 256 thr, 8 warps 2x4, warp tile 64x32, cp.async dbl-buf.
#define SA_STR 20

template<bool BIAS, bool RND>
__global__ __launch_bounds__(256)
void gemm_mma(const float* __restrict__ A, const float* __restrict__ Bt,
              float* __restrict__ C, const float* __restrict__ bias, int M)
{
    __shared__ float As[2][128 * SA_STR];
    __shared__ float Bs[2][128 * SA_STR];

    const int tid  = threadIdx.x;
    const int wid  = tid >> 5, lane = tid & 31;
    const int g    = lane >> 2, tg = lane & 3;
    const int wm   = (wid >> 2) * 64;
    const int wn   = (wid & 3) * 32;
    const int m0   = blockIdx.y * 128, n0 = blockIdx.x * 128;

    float d[4][4][4];
#pragma unroll
    for (int i = 0; i < 4; i++)
#pragma unroll
        for (int j = 0; j < 4; j++)
#pragma unroll
            for (int q = 0; q < 4; q++) d[i][j][q] = 0.f;

    auto issue = [&](int buf, int kt) {
        const int k0 = kt * 16;
#pragma unroll
        for (int e = 0; e < 2; e++) {
            int idx = tid + e * 256;
            int row = idx >> 2, c4 = idx & 3;
            int ga = m0 + row;
            int pa = (ga < M) ? 16 : 0;
            if (ga >= M) ga = M - 1;
            uint32_t da = smem_u32(&As[buf][row * SA_STR + c4 * 4]);
            const float* sa = A + (size_t)ga * 1024u + k0 + c4 * 4;
            asm volatile("cp.async.cg.shared.global [%0], [%1], 16, %2;"
                         :: "r"(da), "l"(sa), "r"(pa));
            uint32_t db = smem_u32(&Bs[buf][row * SA_STR + c4 * 4]);
            const float* sb = Bt + (size_t)(n0 + row) * 1024u + k0 + c4 * 4;
            asm volatile("cp.async.cg.shared.global [%0], [%1], 16;"
                         :: "r"(db), "l"(sb));
        }
        asm volatile("cp.async.commit_group;" ::: "memory");
    };

    issue(0, 0);
    issue(1, 1);

    for (int kt = 0; kt < 64; kt++) {
        const int buf = kt & 1;
        if (kt < 63) asm volatile("cp.async.wait_group 1;" ::: "memory");
        else         asm volatile("cp.async.wait_group 0;" ::: "memory");
        __syncthreads();

#pragma unroll
        for (int ks = 0; ks < 2; ks++) {
            uint32_t af[4][4], bf[4][2];
#pragma unroll
            for (int i = 0; i < 4; i++) {
                const float* base = &As[buf][(wm + i * 16) * SA_STR + ks * 8];
                af[i][0] = __float_as_uint(base[(g)     * SA_STR + tg]);
                af[i][1] = __float_as_uint(base[(g + 8) * SA_STR + tg]);
                af[i][2] = __float_as_uint(base[(g)     * SA_STR + tg + 4]);
                af[i][3] = __float_as_uint(base[(g + 8) * SA_STR + tg + 4]);
            }
#pragma unroll
            for (int j = 0; j < 4; j++) {
                const float* base = &Bs[buf][(wn + j * 8 + g) * SA_STR + ks * 8];
                bf[j][0] = __float_as_uint(base[tg]);
                bf[j][1] = __float_as_uint(base[tg + 4]);
            }
#pragma unroll
            for (int i = 0; i < 4; i++)
#pragma unroll
                for (int j = 0; j < 4; j++)
                    MMA_TF32(d[i][j][0], d[i][j][1], d[i][j][2], d[i][j][3],
                             af[i][0], af[i][1], af[i][2], af[i][3],
                             bf[j][0], bf[j][1]);
        }
        __syncthreads();
        if (kt + 2 < 64) issue(buf, kt + 2);
    }

#pragma unroll
    for (int i = 0; i < 4; i++) {
        const int r0 = m0 + wm + i * 16 + g;
#pragma unroll
        for (int j = 0; j < 4; j++) {
            const int c = n0 + wn + j * 8 + tg * 2;
            float2 v0 = make_float2(d[i][j][0], d[i][j][1]);
            float2 v1 = make_float2(d[i][j][2], d[i][j][3]);
            if (BIAS) {
                const float b0 = bias[c], b1 = bias[c + 1];
                v0.x += b0; v0.y += b1; v1.x += b0; v1.y += b1;
            }
            if (RND) {
                v0.x = rna_tf32(v0.x); v0.y = rna_tf32(v0.y);
                v1.x = rna_tf32(v1.x); v1.y = rna_tf32(v1.y);
            }
            if (r0 < M)     *(float2*)&C[(size_t)r0 * 1024u + c] = v0;
            if (r0 + 8 < M) *(float2*)&C[(size_t)(r0 + 8) * 1024u + c] = v1;
        }
    }
}

// =================== fused flash attention (tf32 mma) ======================
// One CTA per (m-tile of 128, b*h). Q in smem (pre-scaled, rna). KV chunks
// of 64: S-mma -> online softmax (P rna-rounded; l summed over rounded P)
// -> rescale O regs -> PV-mma.  Layouts padded for conflict-free fragments.
#define QS_O 0                        // 128 x 68
#define KS_O (QS_O + 128*68)          // 64 x 68
#define VS_O (KS_O + 64*68)           // 64 x 72
#define SS_O (VS_O + 64*72)           // 128 x 68
#define MR_O (SS_O + 128*68)          // 128
#define LR_O (MR_O + 128)             // 128
#define AR_O (LR_O + 128)             // 128
#define FL_SMEM ((AR_O + 128) * 4)    // bytes = 107008

#define NCHUNK ((KVn + 63) / 64)      // 34

__global__ __launch_bounds__(256, 2)
void flash_attn(const float* __restrict__ Q, const float* __restrict__ K,
                const float* __restrict__ V, float* __restrict__ O)
{
    extern __shared__ float sm[];
    const int tid = threadIdx.x;
    const int wid = tid >> 5, lane = tid & 31;
    const int g = lane >> 2, tg = lane & 3;
    const int bh = blockIdx.y, b = bh >> 4, h = bh & 15;
    const int m0 = blockIdx.x * 128;

    const float* Qb = Q + ((size_t)(b * SEQn + m0)) * 1024u + h * 64;
    const float* Kb = K + ((size_t)b * KVn) * 1024u + h * 64;
    const float* Vb = V + ((size_t)b * KVn) * 1024u + h * 64;

    // Q tile: pre-scale + rna-round
    for (int e = tid; e < 128 * 64; e += 256) {
        int r = e >> 6, c = e & 63;
        sm[QS_O + r * 68 + c] = rna_tf32(Qb[(size_t)r * 1024u + c] * SCALEf);
    }
    if (tid < 128) { sm[MR_O + tid] = -1e30f; sm[LR_O + tid] = 0.f; }

    float oacc[4][2][4];
#pragma unroll
    for (int i = 0; i < 4; i++)
#pragma unroll
        for (int j = 0; j < 2; j++)
#pragma unroll
            for (int q = 0; q < 4; q++) oacc[i][j][q] = 0.f;

    const int om = (wid >> 2) * 64;   // warp m offset
    const int on = (wid & 3) * 16;    // warp n offset (S cols / O cols)
    __syncthreads();

    for (int t = 0; t < NCHUNK; t++) {
        const int kv0 = t * 64;
        const int rows = (KVn - kv0 < 64) ? (KVn - kv0) : 64;

        // ---- load K,V chunk (64 x 64 f32 each) via cp.async ----
#pragma unroll
        for (int e = 0; e < 4; e++) {
            int idx = tid + e * 256;          // 0..1023
            int r = idx >> 4, c4 = idx & 15;
            int kvr = kv0 + r; if (kvr >= KVn) kvr = KVn - 1;
            const float* sk = Kb + (size_t)kvr * 1024u + c4 * 4;
            uint32_t dk = smem_u32(&sm[KS_O + r * 68 + c4 * 4]);
            asm volatile("cp.async.cg.shared.global [%0], [%1], 16;" :: "r"(dk), "l"(sk));
            const float* sv = Vb + (size_t)kvr * 1024u + c4 * 4;
            uint32_t dv = smem_u32(&sm[VS_O + r * 72 + c4 * 4]);
            asm volatile("cp.async.cg.shared.global [%0], [%1], 16;" :: "r"(dv), "l"(sv));
        }
        asm volatile("cp.async.commit_group;" ::: "memory");
        asm volatile("cp.async.wait_group 0;" ::: "memory");
        __syncthreads();

        // ---- S = Qs @ Ks^T  (warp tile 64x16) ----
        float s[4][2][4];
#pragma unroll
        for (int i = 0; i < 4; i++)
#pragma unroll
            for (int j = 0; j < 2; j++)
#pragma unroll
                for (int q = 0; q < 4; q++) s[i][j][q] = 0.f;

#pragma unroll
        for (int ks = 0; ks < 8; ks++) {
            uint32_t af[4][4], bf[2][2];
#pragma unroll
            for (int i = 0; i < 4; i++) {
                const float* base = &sm[QS_O + (om + i * 16) * 68 + ks * 8];
                af[i][0] = __float_as_uint(base[(g)     * 68 + tg]);
                af[i][1] = __float_as_uint(base[(g + 8) * 68 + tg]);
                af[i][2] = __float_as_uint(base[(g)     * 68 + tg + 4]);
                af[i][3] = __float_as_uint(base[(g + 8) * 68 + tg + 4]);
            }
#pragma unroll
            for (int j = 0; j < 2; j++) {
                const float* base = &sm[KS_O + (on + j * 8 + g) * 68 + ks * 8];
                bf[j][0] = __float_as_uint(base[tg]);
                bf[j][1] = __float_as_uint(base[tg + 4]);
            }
#pragma unroll
            for (int i = 0; i < 4; i++)
#pragma unroll
                for (int j = 0; j < 2; j++)
                    MMA_TF32(s[i][j][0], s[i][j][1], s[i][j][2], s[i][j][3],
                             af[i][0], af[i][1], af[i][2], af[i][3],
                             bf[j][0], bf[j][1]);
        }
        // write S fragments to smem
#pragma unroll
        for (int i = 0; i < 4; i++) {
            const int r0 = om + i * 16 + g;
#pragma unroll
            for (int j = 0; j < 2; j++) {
                const int c = on + j * 8 + tg * 2;
                sm[SS_O + r0 * 68 + c]           = s[i][j][0];
                sm[SS_O + r0 * 68 + c + 1]       = s[i][j][1];
                sm[SS_O + (r0 + 8) * 68 + c]     = s[i][j][2];
                sm[SS_O + (r0 + 8) * 68 + c + 1] = s[i][j][3];
            }
        }
        __syncthreads();

        // ---- online softmax: warp handles rows [wid*16, wid*16+16) ----
#pragma unroll 4
        for (int rr = 0; rr < 16; rr++) {
            const int r = wid * 16 + rr;
            const int c0 = lane * 2;
            float v0 = (c0     < rows) ? sm[SS_O + r * 68 + c0]     : -1e30f;
            float v1 = (c0 + 1 < rows) ? sm[SS_O + r * 68 + c0 + 1] : -1e30f;
            float mx = fmaxf(v0, v1);
#pragma unroll
            for (int o = 16; o; o >>= 1) mx = fmaxf(mx, __shfl_xor_sync(~0u, mx, o));
            const float mold = sm[MR_O + r];
            const float mnew = fmaxf(mold, mx);
            float p0 = (c0     < rows) ? rna_tf32(__expf(v0 - mnew)) : 0.f;
            float p1 = (c0 + 1 < rows) ? rna_tf32(__expf(v1 - mnew)) : 0.f;
            sm[SS_O + r * 68 + c0]     = p0;
            sm[SS_O + r * 68 + c0 + 1] = p1;
            float ls = p0 + p1;
#pragma unroll
            for (int o = 16; o; o >>= 1) ls += __shfl_xor_sync(~0u, ls, o);
            if (lane == 0) {
                const float al = __expf(mold - mnew);
                sm[AR_O + r] = al;
                sm[LR_O + r] = sm[LR_O + r] * al + ls;
                sm[MR_O + r] = mnew;
            }
        }
        __syncthreads();

        // ---- rescale O accumulators ----
#pragma unroll
        for (int i = 0; i < 4; i++) {
            const float a0 = sm[AR_O + om + i * 16 + g];
            const float a1 = sm[AR_O + om + i * 16 + g + 8];
#pragma unroll
            for (int j = 0; j < 2; j++) {
                oacc[i][j][0] *= a0; oacc[i][j][1] *= a0;
                oacc[i][j][2] *= a1; oacc[i][j][3] *= a1;
            }
        }

        // ---- O += P @ V  (A = P m128 k64, B = V^T n64 k64) ----
#pragma unroll
        for (int ks = 0; ks < 8; ks++) {
            uint32_t af[4][4], bf[2][2];
#pragma unroll
            for (int i = 0; i < 4; i++) {
                const float* base = &sm[SS_O + (om + i * 16) * 68 + ks * 8];
                af[i][0] = __float_as_uint(base[(g)     * 68 + tg]);
                af[i][1] = __float_as_uint(base[(g + 8) * 68 + tg]);
                af[i][2] = __float_as_uint(base[(g)     * 68 + tg + 4]);
                af[i][3] = __float_as_uint(base[(g + 8) * 68 + tg + 4]);
            }
#pragma unroll
            for (int j = 0; j < 2; j++) {
                bf[j][0] = __float_as_uint(sm[VS_O + (ks * 8 + tg)     * 72 + on + j * 8 + g]);
                bf[j][1] = __float_as_uint(sm[VS_O + (ks * 8 + tg + 4) * 72 + on + j * 8 + g]);
            }
#pragma unroll
            for (int i = 0; i < 4; i++)
#pragma unroll
                for (int j = 0; j < 2; j++)
                    MMA_TF32(oacc[i][j][0], oacc[i][j][1], oacc[i][j][2], oacc[i][j][3],
                             af[i][0], af[i][1], af[i][2], af[i][3],
                             bf[j][0], bf[j][1]);
        }
        __syncthreads();
    }

    // ---- epilogue: O / l, rna-round for out-projection ----
    float* Ob = O + ((size_t)(b * SEQn + m0)) * 1024u + h * 64;
#pragma unroll
    for (int i = 0; i < 4; i++) {
        const int r0 = om + i * 16 + g;
        const float li0 = 1.f / sm[LR_O + r0];
        const float li1 = 1.f / sm[LR_O + r0 + 8];
#pragma unroll
        for (int j = 0; j < 2; j++) {
            const int c = on + j * 8 + tg * 2;
            float2 v0 = make_float2(rna_tf32(oacc[i][j][0] * li0), rna_tf32(oacc[i][j][1] * li0));
            float2 v1 = make_float2(rna_tf32(oacc[i][j][2] * li1), rna_tf32(oacc[i][j][3] * li1));
            *(float2*)&Ob[(size_t)r0 * 1024u + c]       = v0;
            *(float2*)&Ob[(size_t)(r0 + 8) * 1024u + c] = v1;
        }
    }
}

// ---------------- weight transpose + tf32 round ---------------------------
__global__ void transpose_1024(const float* __restrict__ W, float* __restrict__ Wt)
{
    __shared__ float t[32][33];
    const int bx = blockIdx.x * 32, by = blockIdx.y * 32;
    const int tx = threadIdx.x, ty = threadIdx.y;
#pragma unroll
    for (int i = 0; i < 4; i++)
        t[ty + i * 8][tx] = W[(size_t)(by + ty + i * 8) * 1024 + bx + tx];
    __syncthreads();
#pragma unroll
    for (int i = 0; i < 4; i++)
        Wt[(size_t)(bx + ty + i * 8) * 1024 + by + tx] = rna_tf32(t[tx][ty + i * 8]);
}

// ---------------- tf32 rounding copy ---------------------------------------
__global__ void round_copy(const float4* __restrict__ in, float4* __restrict__ out, int n4)
{
    int i = blockIdx.x * blockDim.x + threadIdx.x;
    if (i < n4) {
        float4 v = in[i];
        v.x = rna_tf32(v.x); v.y = rna_tf32(v.y);
        v.z = rna_tf32(v.z); v.w = rna_tf32(v.w);
        out[i] = v;
    }
}

// ---------------- rotary on Q ---------------------------------------------
__global__ void rotary_q_kernel(float* __restrict__ Q, const float* __restrict__ freqs,
                                const int* __restrict__ cur)
{
    const int row = blockIdx.x;
    const int s   = row % SEQn;
    const int p   = threadIdx.x;
    const int col0 = 2*p;
    const int d0   = col0 & 63;

    const int cp = cur[0];
    const int inner = cp % 16;
    const int rs = inner % 4, cs = inner / 4;
    const int fr = rs*16 + (s >> 4), fc = cs*16 + (s & 15);
    const float* f = freqs + ((fr<<6) + fc) * 64;
    const float f0 = f[d0], f1 = f[d0+1];

    float* q = Q + (long long)row*INNERn + col0;
    const float t0 = q[0], t1 = q[1];
    q[0] = t0*cosf(f0) - t1*sinf(f0);
    q[1] = t1*cosf(f1) + t0*sinf(f1);
}

// ---------------- bias + rotary on memory K rows ---------------------------
__global__ void biasrot_k_kernel(float* __restrict__ K, const float* __restrict__ freqs,
                                 const float* __restrict__ rel_table,
                                 const int* __restrict__ memidx,
                                 const int* __restrict__ cur)
{
    const int gid = blockIdx.x;
    const int b = gid / MSn;
    const int j = gid - b*MSn;
    const int m = j >> 8;
    const int jj = j & 255;

    const int p = threadIdx.x;
    const int col0 = 2*p;
    const int h  = col0 >> 6;
    const int d0 = col0 & 63;

    const int cp = cur[0];
    const int ci = cp % 16;
    const int rs = ci % 4, cs = ci / 4, ts = cp / 16;
    const int mi = memidx[m];
    const int mn = mi % 16;
    const int rt = mn % 4, ct = mn / 4, tt = mi / 16;
    const int rel = (rt - rs + 4)*9 + (ct - cs + 4) + (tt - ts + 4)*81;
    const float bias = rel_table[rel*HEADSn + h];

    const int fr = rt*16 + (jj >> 4), fc = ct*16 + (jj & 15);
    const float* f = freqs + ((fr<<6) + fc) * 64;
    const float f0 = f[d0], f1 = f[d0+1];

    float* kp = K + ((long long)b*KVn + j)*INNERn + col0;
    const float t0 = kp[0] + bias, t1 = kp[1] + bias;
    kp[0] = t0*cosf(f0) - t1*sinf(f0);
    kp[1] = t1*cosf(f1) + t0*sinf(f1);
}

// ---------------- host launch ----------------------------------------------
extern "C" void kernel_launch(void* const* d_in, const int* in_sizes, int n_in,
                              void* d_out, int out_size)
{
    const float* x     = (const float*)d_in[0];
    const float* cond  = (const float*)d_in[1];
    const float* freqs = (const float*)d_in[2];
    const float* Wq    = (const float*)d_in[3];
    const float* Wk    = (const float*)d_in[4];
    const float* Wv    = (const float*)d_in[5];
    const float* rel   = (const float*)d_in[6];
    const float* Wo    = (const float*)d_in[7];
    const float* bo    = (const float*)d_in[8];
    const int*   memi  = (const int*)d_in[9];
    const int*   cur   = (const int*)d_in[10];
    float* out = (float*)d_out;

    float *Qb, *Kb, *Vb, *Ob, *Wt, *Xr, *Cr;
    cudaGetSymbolAddress((void**)&Qb, g_Q);
    cudaGetSymbolAddress((void**)&Kb, g_K);
    cudaGetSymbolAddress((void**)&Vb, g_V);
    cudaGetSymbolAddress((void**)&Ob, g_O);
    cudaGetSymbolAddress((void**)&Wt, g_Wt);
    cudaGetSymbolAddress((void**)&Xr, g_Xr);
    cudaGetSymbolAddress((void**)&Cr, g_Cr);

    cudaFuncSetAttribute(flash_attn, cudaFuncAttributeMaxDynamicSharedMemorySize, FL_SMEM);

    float* Wtq = Wt + 0LL * DIMn * INNERn;
    float* Wtk = Wt + 1LL * DIMn * INNERn;
    float* Wtv = Wt + 2LL * DIMn * INNERn;
    float* Wto = Wt + 3LL * DIMn * INNERn;

    // 0) tf32-round activations; transpose+round weights to K-major [N][K]
    round_copy<<<(ROWS_X*DIMn/4 + 255)/256, 256>>>((const float4*)x,    (float4*)Xr, ROWS_X*DIMn/4);
    round_copy<<<(ROWS_C*DIMn/4 + 255)/256, 256>>>((const float4*)cond, (float4*)Cr, ROWS_C*DIMn/4);
    transpose_1024<<<dim3(32,32), dim3(32,8)>>>(Wq, Wtq);
    transpose_1024<<<dim3(32,32), dim3(32,8)>>>(Wk, Wtk);
    transpose_1024<<<dim3(32,32), dim3(32,8)>>>(Wv, Wtv);
    transpose_1024<<<dim3(32,32), dim3(32,8)>>>(Wo, Wto);

    // 1-3) projections on tf32 tensor cores (V rna-rounded for PV mma)
    gemm_mma<false,false><<<dim3(8, 32),  256>>>(Xr, Wtq, Qb, nullptr, ROWS_X);
    gemm_mma<false,false><<<dim3(8, 266), 256>>>(Cr, Wtk, Kb, nullptr, ROWS_C);
    gemm_mma<false,true ><<<dim3(8, 266), 256>>>(Cr, Wtv, Vb, nullptr, ROWS_C);

    // 4) rotary(Q)
    rotary_q_kernel<<<ROWS_X, 512>>>(Qb, freqs, cur);

    // 5) bias + rotary on memory K rows
    biasrot_k_kernel<<<Bn*MSn, 512>>>(Kb, freqs, rel, memi, cur);

    // 6-8) fused flash attention (tf32 mma, online softmax), writes rna(O)
    flash_attn<<<dim3(2, BHn), 256, FL_SMEM>>>(Qb, Kb, Vb, Ob);

    // 9) out = O @ Wo + bo  (tf32 tensor cores, bias epilogue)
    gemm_mma<true,false><<<dim3(8, 32), 256>>>(Ob, Wto, out, bo, ROWS_X);
}